// round 16
// baseline (speedup 1.0000x reference)
#include <cuda_runtime.h>
#include <math.h>
#include <stdint.h>

#define Bz  32
#define Sz  48
#define Vz  10000
#define CVz 9600
#define Hz  768
#define NHz 12
#define NLz 12
#define Gz  32
#define HDz 64
#define CPG (Hz/Gz)   // 24

// ------------------------- scratch (no allocation allowed) -------------------------
__device__ float g_h  [Bz*Sz*Hz];
__device__ float g_x  [Bz*Sz*Hz];
__device__ float g_qkv[Bz*Sz*3*Hz];
__device__ float g_a  [Bz*Sz*Hz];
__device__ float g_mlp[Bz*Sz*4*Hz];
__device__ float g_cat[Bz*(Sz-1)*2*Hz];
__device__ float g_a1 [Bz*(Sz-1)*2*Hz];

// ------------------------- helpers -------------------------
__device__ __forceinline__ void mma_tf32(float c[4],
                                         uint32_t a0, uint32_t a1, uint32_t a2, uint32_t a3,
                                         uint32_t b0, uint32_t b1) {
    asm volatile(
        "mma.sync.aligned.m16n8k8.row.col.f32.tf32.tf32.f32 "
        "{%0,%1,%2,%3},{%4,%5,%6,%7},{%8,%9},{%0,%1,%2,%3};"
        : "+f"(c[0]), "+f"(c[1]), "+f"(c[2]), "+f"(c[3])
        : "r"(a0), "r"(a1), "r"(a2), "r"(a3), "r"(b0), "r"(b1));
}

__device__ __forceinline__ void cp_async16(void* smem, const void* gmem, bool pred) {
    uint32_t s = (uint32_t)__cvta_generic_to_shared(smem);
    int src_bytes = pred ? 16 : 0;   // 0 -> zero-fill
    asm volatile("cp.async.cg.shared.global [%0], [%1], 16, %2;\n"
                 :: "r"(s), "l"(gmem), "r"(src_bytes));
}
__device__ __forceinline__ void cp_commit() { asm volatile("cp.async.commit_group;\n"); }
__device__ __forceinline__ void cp_wait3()  { asm volatile("cp.async.wait_group 3;\n"); }

__device__ __forceinline__ float tanh_fast(float x) {
    float y;
    asm("tanh.approx.f32 %0, %1;" : "=f"(y) : "f"(x));
    return y;
}

__device__ __forceinline__ float apply_act(float v, const float* __restrict__ bias,
                                           const float* __restrict__ res,
                                           int gr, int gc, int N, int mode) {
    if (mode & 1)  v += bias[gc];
    if (mode & 2)  v += res[(size_t)gr * N + gc];
    if (mode & 4) {                       // gelu via HW tanh.approx
        float x = v;
        float th = tanh_fast(0.7978845608028654f * (x + 0.044715f * x * x * x));
        v = 0.5f * x * (1.f + th);
    }
    if (mode & 8)  v = fmaxf(v, 0.f);
    if (mode & 16) v = 0.5f + 0.5f * tanh_fast(0.5f * v);  // sigmoid via tanh
    return v;
}

// ------------------- sparse embedding + pos embed (float4 scan + gather) -------------------
__global__ void embed_kernel(const float* __restrict__ visits,
                             const float* __restrict__ vemb,
                             const float* __restrict__ pemb,
                             float* __restrict__ out)
{
    int row = blockIdx.x;            // b*Sz + s
    int s   = row % Sz;
    const float4* vrow4 = (const float4*)(visits + (size_t)row * Vz);
    int t = threadIdx.x;             // 192 threads
    const float4* pemb4 = (const float4*)pemb;
    const float4* vemb4 = (const float4*)vemb;
    float4 acc = pemb4[s * 192 + t];

    __shared__ int   s_idx[768];
    __shared__ float s_val[768];
    __shared__ int   wcnt[6];

    int lane = t & 31, w = t >> 5;   // 6 warps
    const int V4 = Vz / 4;           // 2500

    for (int base = 0; base < V4; base += 192) {
        __syncthreads();
        int v4 = base + t;
        float4 val = (v4 < V4) ? vrow4[v4] : make_float4(0.f, 0.f, 0.f, 0.f);
        int nz = (val.x != 0.f) + (val.y != 0.f) + (val.z != 0.f) + (val.w != 0.f);
        int pre = nz;
#pragma unroll
        for (int o = 1; o < 32; o <<= 1) {
            int up = __shfl_up_sync(0xffffffffu, pre, o);
            if (lane >= o) pre += up;
        }
        int wtot = __shfl_sync(0xffffffffu, pre, 31);
        if (lane == 31) wcnt[w] = wtot;
        __syncthreads();
        int off = pre - nz;
#pragma unroll
        for (int i = 0; i < 6; i++) { if (i < w) off += wcnt[i]; }
        int cnt = 0;
#pragma unroll
        for (int i = 0; i < 6; i++) cnt += wcnt[i];
        if (nz) {
            int p = off;
            int vb = v4 * 4;
            if (val.x != 0.f) { s_idx[p] = vb;     s_val[p] = val.x; p++; }
            if (val.y != 0.f) { s_idx[p] = vb + 1; s_val[p] = val.y; p++; }
            if (val.z != 0.f) { s_idx[p] = vb + 2; s_val[p] = val.z; p++; }
            if (val.w != 0.f) { s_idx[p] = vb + 3; s_val[p] = val.w; p++; }
        }
        __syncthreads();
        for (int j = 0; j < cnt; j++) {
            float4 er = vemb4[(size_t)s_idx[j] * 192 + t];
            float vv = s_val[j];
            acc.x += vv * er.x; acc.y += vv * er.y;
            acc.z += vv * er.z; acc.w += vv * er.w;
        }
    }
    ((float4*)(out + (size_t)row * Hz))[t] = acc;
}

// ---------------- group norm: single pass, register-cached, 2 groups per CTA ----------------
template<bool CAT>
__global__ void groupnorm_kernel(const float* __restrict__ in, float* __restrict__ out,
                                 const float* __restrict__ w, const float* __restrict__ b)
{
    int t = threadIdx.x;             // 256
    int half = t >> 7;               // 0/1
    int tl = t & 127;
    int bg = blockIdx.x * 2 + half;
    int bt = bg / Gz, g = bg % Gz;
    int lane = tl & 31, wid = tl >> 5;
    const int NELEM = Sz * CPG;      // 1152

    float4 v0, v1, v2;
    int i0 = tl, i1 = tl + 128, i2 = tl + 256;
    {
        int s = i0 / 6, c4 = i0 % 6;
        v0 = *(const float4*)&in[((size_t)bt*Sz + s)*Hz + g*CPG + c4*4];
        s = i1 / 6; c4 = i1 % 6;
        v1 = *(const float4*)&in[((size_t)bt*Sz + s)*Hz + g*CPG + c4*4];
        if (tl < 32) {
            s = i2 / 6; c4 = i2 % 6;
            v2 = *(const float4*)&in[((size_t)bt*Sz + s)*Hz + g*CPG + c4*4];
        }
    }
    float sum = v0.x+v0.y+v0.z+v0.w + v1.x+v1.y+v1.z+v1.w;
    float sq  = v0.x*v0.x+v0.y*v0.y+v0.z*v0.z+v0.w*v0.w
              + v1.x*v1.x+v1.y*v1.y+v1.z*v1.z+v1.w*v1.w;
    if (tl < 32) {
        sum += v2.x+v2.y+v2.z+v2.w;
        sq  += v2.x*v2.x+v2.y*v2.y+v2.z*v2.z+v2.w*v2.w;
    }
#pragma unroll
    for (int o = 16; o > 0; o >>= 1) {
        sum += __shfl_xor_sync(0xffffffffu, sum, o);
        sq  += __shfl_xor_sync(0xffffffffu, sq,  o);
    }
    __shared__ float r1[8], r2[8];
    if (lane == 0) { r1[half*4 + wid] = sum; r2[half*4 + wid] = sq; }
    __syncthreads();
    float tot  = r1[half*4+0] + r1[half*4+1] + r1[half*4+2] + r1[half*4+3];
    float tot2 = r2[half*4+0] + r2[half*4+1] + r2[half*4+2] + r2[half*4+3];
    float mean = tot / NELEM;
    float var  = tot2 / NELEM - mean*mean;
    float inv  = rsqrtf(var + 1e-5f);

    auto emit = [&](int idx, float4 v) {
        int s = idx / 6, c4 = idx % 6;
        int ch = g*CPG + c4*4;
        float4 o4;
        o4.x = (v.x - mean) * inv * w[ch+0] + b[ch+0];
        o4.y = (v.y - mean) * inv * w[ch+1] + b[ch+1];
        o4.z = (v.z - mean) * inv * w[ch+2] + b[ch+2];
        o4.w = (v.w - mean) * inv * w[ch+3] + b[ch+3];
        if (!CAT) {
            *(float4*)&out[((size_t)bt*Sz + s)*Hz + ch] = o4;
        } else {
            if (s < Sz-1)
                *(float4*)&out[((size_t)(bt*(Sz-1) + s))*2*Hz + ch] = o4;
            if (s > 0)
                *(float4*)&out[((size_t)(bt*(Sz-1) + s - 1))*2*Hz + Hz + ch] = o4;
        }
    };
    emit(i0, v0);
    emit(i1, v1);
    if (tl < 32) emit(i2, v2);
}

// ==================== 5-stage pipelined tf32 GEMM — permuted-k fragments ====================
// Physical k for mma slot (tig, half, step s) = 4*tig + 2*s + half.
#define STG  5

template<int BM, int BN, int MINB>
__global__ __launch_bounds__(256, MINB)
void gemm_tc_kernel(const float* __restrict__ A, const float* __restrict__ W,
                    const float* __restrict__ bias, const float* __restrict__ res,
                    float* __restrict__ C, int M, int N, int K, int mode)
{
    constexpr int WN = BN / 32;
    constexpr int WM = 8 / WN;
    constexpr int MI = BM / (WM * 16);
    constexpr int A_ELE = BM * 16;
    constexpr int B_ELE = 16 * BN;
    extern __shared__ float smem[];
    float* sAb = smem;                 // [STG][BM][16]
    float* sBb = smem + STG * A_ELE;   // [STG][16][BN] (chunk-swizzled)

    int t = threadIdx.x;
    int bm = blockIdx.y * BM;
    int bn = blockIdx.x * BN;
    int lane = t & 31, w = t >> 5;
    int wm = w % WM, wn = w / WM;
    int m_base = wm * (BM / WM), n_base = wn * 32;
    int g = lane >> 2, tig = lane & 3;
    const int xorv = 2 * tig;

    float acc[MI][4][4];
#pragma unroll
    for (int i = 0; i < MI; i++)
#pragma unroll
        for (int j = 0; j < 4; j++)
#pragma unroll
            for (int q = 0; q < 4; q++) acc[i][j][q] = 0.f;

    const int KT = K / 16;

    auto load_tile = [&](int st, int kt) {
        int k0 = kt * 16;
        float* sA = sAb + st * A_ELE;
        float* sB = sBb + st * B_ELE;
#pragma unroll
        for (int idx = t; idx < BM * 4; idx += 256) {
            int mr = idx >> 2;
            int c  = idx & 3;
            cp_async16(sA + mr * 16 + c * 4, A + (size_t)(bm + mr) * K + k0 + c * 4, bm + mr < M);
        }
#pragma unroll
        for (int idx = t; idx < BN * 4; idx += 256) {
            int kr = idx / (BN / 4);
            int nc = idx % (BN / 4);
            int nc2 = nc ^ ((2 * (kr >> 2)) & 7);
            cp_async16(sB + kr * BN + nc2 * 4, W + (size_t)(k0 + kr) * N + bn + nc * 4, true);
        }
    };

#pragma unroll
    for (int s = 0; s < 4; s++) { load_tile(s, s); cp_commit(); }

    int st_c = 0, st_l = 4;
    for (int kt = 0; kt < KT; kt++) {
        cp_wait3();            // all but 3 most recent groups complete => tile kt ready
        __syncthreads();
        if (kt + 4 < KT) load_tile(st_l, kt + 4);
        cp_commit();           // unconditional: keeps "3 most recent" = kt+1..kt+3

        const float* sA = sAb + st_c * A_ELE;
        const float* sB = sBb + st_c * B_ELE;

        float4 fa[MI][2];
#pragma unroll
        for (int mi = 0; mi < MI; mi++) {
            int m0 = m_base + mi * 16;
            fa[mi][0] = *(const float4*)(sA + (m0 + g    ) * 16 + 4 * tig);
            fa[mi][1] = *(const float4*)(sA + (m0 + g + 8) * 16 + 4 * tig);
        }
#pragma unroll
        for (int s = 0; s < 2; s++) {
            int kb = 4 * tig + 2 * s;
            uint32_t bf[4][2];
#pragma unroll
            for (int ni = 0; ni < 4; ni++) {
                int chunk = ((n_base + ni * 8) >> 2) + (g >> 2);
                int col = ((chunk ^ xorv) << 2) + (g & 3);
                bf[ni][0] = __float_as_uint(sB[kb * BN + col]);
                bf[ni][1] = __float_as_uint(sB[(kb + 1) * BN + col]);
            }
#pragma unroll
            for (int mi = 0; mi < MI; mi++) {
                uint32_t a0 = __float_as_uint(s ? fa[mi][0].z : fa[mi][0].x);
                uint32_t a1 = __float_as_uint(s ? fa[mi][1].z : fa[mi][1].x);
                uint32_t a2 = __float_as_uint(s ? fa[mi][0].w : fa[mi][0].y);
                uint32_t a3 = __float_as_uint(s ? fa[mi][1].w : fa[mi][1].y);
#pragma unroll
                for (int ni = 0; ni < 4; ni++)
                    mma_tf32(acc[mi][ni], a0, a1, a2, a3, bf[ni][0], bf[ni][1]);
            }
        }
        st_c = (st_c == STG-1) ? 0 : st_c + 1;
        st_l = (st_l == STG-1) ? 0 : st_l + 1;
    }

    // epilogue
#pragma unroll
    for (int mi = 0; mi < MI; mi++) {
        int gr0 = bm + m_base + mi * 16 + g;
        int gr1 = gr0 + 8;
#pragma unroll
        for (int ni = 0; ni < 4; ni++) {
            int gc = bn + n_base + ni * 8 + 2 * tig;
            if (gr0 < M) {
                float v0 = apply_act(acc[mi][ni][0], bias, res, gr0, gc,     N, mode);
                float v1 = apply_act(acc[mi][ni][1], bias, res, gr0, gc + 1, N, mode);
                *(float2*)(C + (size_t)gr0 * N + gc) = make_float2(v0, v1);
            }
            if (gr1 < M) {
                float v2 = apply_act(acc[mi][ni][2], bias, res, gr1, gc,     N, mode);
                float v3 = apply_act(acc[mi][ni][3], bias, res, gr1, gc + 1, N, mode);
                *(float2*)(C + (size_t)gr1 * N + gc) = make_float2(v2, v3);
            }
        }
    }
}

// ======== masked-transposed GEMM (head): C = act(A[M,K] @ (tril(W[N,K]))^T + bias) ========
__global__ __launch_bounds__(256, 2)
void gemm_t_tc_kernel(const float* __restrict__ A, const float* __restrict__ Wr,
                      const float* __restrict__ bias,
                      float* __restrict__ C, int M, int N, int K, int mode)
{
    constexpr int BM = 128, MI = 4;
    constexpr int A_ELE = 128 * 16;
    extern __shared__ float smem[];
    float* sAb  = smem;
    float* sBTb = smem + STG * A_ELE;   // [STG][128][16] ([n][k])

    int t = threadIdx.x;
    int bm = blockIdx.y * BM;
    int bn = blockIdx.x * 128;
    int lane = t & 31, w = t >> 5;
    int wm = w & 1, wn = w >> 1;
    int m_base = wm * 64, n_base = wn * 32;
    int g = lane >> 2, tig = lane & 3;
    const bool need_mask = (bn < K);

    float acc[MI][4][4];
#pragma unroll
    for (int i = 0; i < MI; i++)
#pragma unroll
        for (int j = 0; j < 4; j++)
#pragma unroll
            for (int q = 0; q < 4; q++) acc[i][j][q] = 0.f;

    int KT = K / 16;
    if (need_mask) {
        int need = (bn + 127) / 16 + 1;
        KT = KT < need ? KT : need;
    }

    auto load_tile = [&](int st, int kt) {
        int k0 = kt * 16;
        float* sA  = sAb  + st * A_ELE;
        float* sBT = sBTb + st * A_ELE;
#pragma unroll
        for (int it = 0; it < 2; it++) {
            int idx = it * 256 + t;
            int mr = idx >> 2;
            int c  = idx & 3;
            cp_async16(sA + mr * 16 + c * 4, A + (size_t)(bm + mr) * K + k0 + c * 4, bm + mr < M);
        }
#pragma unroll
        for (int it = 0; it < 2; it++) {
            int idx = it * 256 + t;
            int n  = idx >> 2;
            int c  = idx & 3;
            cp_async16(sBT + n * 16 + c * 4, Wr + (size_t)(bn + n) * K + k0 + c * 4, true);
        }
    };

#pragma unroll
    for (int s = 0; s < 4; s++) { load_tile(s, s); cp_commit(); }

    int st_c = 0, st_l = 4;
    for (int kt = 0; kt < KT; kt++) {
        cp_wait3();
        __syncthreads();
        if (kt + 4 < KT) load_tile(st_l, kt + 4);
        cp_commit();

        int k0 = kt * 16;
        const float* sA  = sAb  + st_c * A_ELE;
        const float* sBT = sBTb + st_c * A_ELE;

        float4 fa[MI][2];
#pragma unroll
        for (int mi = 0; mi < MI; mi++) {
            int m0 = m_base + mi * 16;
            fa[mi][0] = *(const float4*)(sA + (m0 + g    ) * 16 + 4 * tig);
            fa[mi][1] = *(const float4*)(sA + (m0 + g + 8) * 16 + 4 * tig);
        }
        float4 fb[4];
        int kb = k0 + 4 * tig;
#pragma unroll
        for (int ni = 0; ni < 4; ni++) {
            int nl = n_base + ni * 8 + g;
            fb[ni] = *(const float4*)(sBT + nl * 16 + 4 * tig);
            if (need_mask) {
                int gn = bn + nl;
                if (kb     > gn) fb[ni].x = 0.f;
                if (kb + 1 > gn) fb[ni].y = 0.f;
                if (kb + 2 > gn) fb[ni].z = 0.f;
                if (kb + 3 > gn) fb[ni].w = 0.f;
            }
        }
#pragma unroll
        for (int s = 0; s < 2; s++) {
#pragma unroll
            for (int mi = 0; mi < MI; mi++) {
                uint32_t a0 = __float_as_uint(s ? fa[mi][0].z : fa[mi][0].x);
                uint32_t a1 = __float_as_uint(s ? fa[mi][1].z : fa[mi][1].x);
                uint32_t a2 = __float_as_uint(s ? fa[mi][0].w : fa[mi][0].y);
                uint32_t a3 = __float_as_uint(s ? fa[mi][1].w : fa[mi][1].y);
#pragma unroll
                for (int ni = 0; ni < 4; ni++) {
                    uint32_t b0 = __float_as_uint(s ? fb[ni].z : fb[ni].x);
                    uint32_t b1 = __float_as_uint(s ? fb[ni].w : fb[ni].y);
                    mma_tf32(acc[mi][ni], a0, a1, a2, a3, b0, b1);
                }
            }
        }
        st_c = (st_c == STG-1) ? 0 : st_c + 1;
        st_l = (st_l == STG-1) ? 0 : st_l + 1;
    }

#pragma unroll
    for (int mi = 0; mi < MI; mi++) {
        int gr0 = bm + m_base + mi * 16 + g;
        int gr1 = gr0 + 8;
#pragma unroll
        for (int ni = 0; ni < 4; ni++) {
            int gc = bn + n_base + ni * 8 + 2 * tig;
            if (gr0 < M) {
                float v0 = apply_act(acc[mi][ni][0], bias, nullptr, gr0, gc,     N, mode);
                float v1 = apply_act(acc[mi][ni][1], bias, nullptr, gr0, gc + 1, N, mode);
                *(float2*)(C + (size_t)gr0 * N + gc) = make_float2(v0, v1);
            }
            if (gr1 < M) {
                float v2 = apply_act(acc[mi][ni][2], bias, nullptr, gr1, gc,     N, mode);
                float v3 = apply_act(acc[mi][ni][3], bias, nullptr, gr1, gc + 1, N, mode);
                *(float2*)(C + (size_t)gr1 * N + gc) = make_float2(v2, v3);
            }
        }
    }
}

// ------------- attention: 6 rows/warp, causal-trimmed QK + PV, warp-local softmax -------------
__global__ void attn_kernel(const float* __restrict__ qkv, float* __restrict__ out)
{
    int bh = blockIdx.x;
    int b = bh / NHz, hd = bh % NHz;
    __shared__ float sq[Sz][68], sk[Sz][68], sv[Sz][68];
    __shared__ float sp[Sz][49];
    int t = threadIdx.x;   // 256
    int lane = t & 31, wid = t >> 5;

    const float* base = qkv + (size_t)b * Sz * (3*Hz) + hd * HDz;
    for (int idx = t; idx < Sz * 16; idx += 256) {
        int s = idx >> 4, d4 = idx & 15;
        const float4* src = (const float4*)(base + (size_t)s * (3*Hz));
        *(float4*)&sq[s][d4*4] = src[d4];
        *(float4*)&sk[s][d4*4] = src[d4 + Hz/4];
        *(float4*)&sv[s][d4*4] = src[d4 + 2*Hz/4];
    }
    __syncthreads();

    const int i0 = wid * 6;
    const int imax = i0 + 5;
    const int j1 = lane, j2 = lane + 32;
    const bool has2 = (j2 <= imax);

    float a0[6] = {0,0,0,0,0,0}, a1r[6] = {0,0,0,0,0,0};
    if (has2) {
#pragma unroll
        for (int d4 = 0; d4 < 16; d4++) {
            float4 k1 = *(const float4*)&sk[j1][d4*4];
            float4 k2 = *(const float4*)&sk[j2][d4*4];
#pragma unroll
            for (int r = 0; r < 6; r++) {
                float4 q = *(const float4*)&sq[i0 + r][d4*4];
                a0[r] += q.x*k1.x + q.y*k1.y + q.z*k1.z + q.w*k1.w;
                a1r[r] += q.x*k2.x + q.y*k2.y + q.z*k2.z + q.w*k2.w;
            }
        }
    } else {
#pragma unroll
        for (int d4 = 0; d4 < 16; d4++) {
            float4 k1 = *(const float4*)&sk[j1][d4*4];
#pragma unroll
            for (int r = 0; r < 6; r++) {
                float4 q = *(const float4*)&sq[i0 + r][d4*4];
                a0[r] += q.x*k1.x + q.y*k1.y + q.z*k1.z + q.w*k1.w;
            }
        }
    }

#pragma unroll
    for (int r = 0; r < 6; r++) {
        int i = i0 + r;
        float s0 = (j1 <= i) ? a0[r] * 0.125f : -1e30f;
        float s1 = (has2 && j2 <= i) ? a1r[r] * 0.125f : -1e30f;
        float mx = fmaxf(s0, s1);
#pragma unroll
        for (int o = 16; o > 0; o >>= 1) mx = fmaxf(mx, __shfl_xor_sync(0xffffffffu, mx, o));
        float e0 = (j1 <= i) ? __expf(s0 - mx) : 0.f;
        float e1 = (has2 && j2 <= i) ? __expf(s1 - mx) : 0.f;
        float sum = e0 + e1;
#pragma unroll
        for (int o = 16; o > 0; o >>= 1) sum += __shfl_xor_sync(0xffffffffu, sum, o);
        float inv = 1.f / sum;
        sp[i][j1] = e0 * inv;
        if (has2) sp[i][j2] = e1 * inv;
    }
    __syncwarp();

    float o0[6] = {0,0,0,0,0,0}, o1[6] = {0,0,0,0,0,0};
    const int jmax = imax + 1;
#pragma unroll 6
    for (int j = 0; j < jmax; j++) {
        float v0 = sv[j][lane];
        float v1 = sv[j][lane + 32];
#pragma unroll
        for (int r = 0; r < 6; r++) {
            float p = sp[i0 + r][j];
            o0[r] += p * v0;
            o1[r] += p * v1;
        }
    }
    float* ob = out + (size_t)b * Sz * Hz + hd * HDz;
#pragma unroll
    for (int r = 0; r < 6; r++) {
        ob[(size_t)(i0 + r) * Hz + lane]      = o0[r];
        ob[(size_t)(i0 + r) * Hz + lane + 32] = o1[r];
    }
}

// ------------------------- launch -------------------------
extern "C" void kernel_launch(void* const* d_in, const int* in_sizes, int n_in,
                              void* d_out, int out_size)
{
    const float* visits = (const float*)d_in[0];
    const float* vemb   = (const float*)d_in[1];
    const float* pemb   = (const float*)d_in[2];
    const float* ln1w   = (const float*)d_in[3];
    const float* ln1b   = (const float*)d_in[4];
    const float* attnw  = (const float*)d_in[5];
    const float* attnb  = (const float*)d_in[6];
    const float* projw  = (const float*)d_in[7];
    const float* projb  = (const float*)d_in[8];
    const float* ln2w   = (const float*)d_in[9];
    const float* ln2b   = (const float*)d_in[10];
    const float* fcw    = (const float*)d_in[11];
    const float* fcb    = (const float*)d_in[12];
    const float* mprojw = (const float*)d_in[13];
    const float* mprojb = (const float*)d_in[14];
    const float* lnfw   = (const float*)d_in[15];
    const float* lnfb   = (const float*)d_in[16];
    const float* a1w    = (const float*)d_in[17];
    const float* a1b    = (const float*)d_in[18];
    const float* a2w    = (const float*)d_in[19];
    const float* a2b    = (const float*)d_in[20];
    float* out = (float*)d_out;

    float *ph, *px, *pqkv, *pa, *pmlp, *pcat, *pa1;
    cudaGetSymbolAddress((void**)&ph,   g_h);
    cudaGetSymbolAddress((void**)&px,   g_x);
    cudaGetSymbolAddress((void**)&pqkv, g_qkv);
    cudaGetSymbolAddress((void**)&pa,   g_a);
    cudaGetSymbolAddress((void**)&pmlp, g_mlp);
    cudaGetSymbolAddress((void**)&pcat, g_cat);
    cudaGetSymbolAddress((void**)&pa1,  g_a1);

    // dynamic smem sizes (5-stage, compact layouts)
    const int SMQ   = STG * ( 96*16 + 16*128) * 4;   // 71680 B (96x128)
    const int SM128 = STG * (128*16 + 16*128) * 4;   // 81920 B
    const int SM64  = STG * ( 64*16 + 16* 64) * 4;   // 40960 B (64x64)
    const int SMT   = STG * (128*16 * 2) * 4;        // 81920 B
    cudaFuncSetAttribute(gemm_tc_kernel<96,128,2>,  cudaFuncAttributeMaxDynamicSharedMemorySize, SMQ);
    cudaFuncSetAttribute(gemm_tc_kernel<128,128,2>, cudaFuncAttributeMaxDynamicSharedMemorySize, SM128);
    cudaFuncSetAttribute(gemm_tc_kernel<64,64,4>,   cudaFuncAttributeMaxDynamicSharedMemorySize, SM64);
    cudaFuncSetAttribute(gemm_t_tc_kernel,          cudaFuncAttributeMaxDynamicSharedMemorySize, SMT);

    const int M = Bz * Sz;   // 1536

    embed_kernel<<<Bz*Sz, 192>>>(visits, vemb, pemb, ph);

    for (int l = 0; l < NLz; l++) {
        groupnorm_kernel<false><<<Bz*Gz/2, 256>>>(ph, px, ln1w + l*Hz, ln1b + l*Hz);
        gemm_tc_kernel<96,128,2><<<dim3(3*Hz/128, M/96), 256, SMQ>>>(
            px, attnw + (size_t)l*Hz*3*Hz, attnb + (size_t)l*3*Hz, nullptr,
            pqkv, M, 3*Hz, Hz, 1);
        attn_kernel<<<Bz*NHz, 256>>>(pqkv, pa);
        gemm_tc_kernel<64,64,4><<<dim3(Hz/64, M/64), 256, SM64>>>(
            pa, projw + (size_t)l*Hz*Hz, projb + (size_t)l*Hz, ph,
            ph, M, Hz, Hz, 1|2);
        groupnorm_kernel<false><<<Bz*Gz/2, 256>>>(ph, px, ln2w + l*Hz, ln2b + l*Hz);
        gemm_tc_kernel<128,128,2><<<dim3(4*Hz/128, M/128), 256, SM128>>>(
            px, fcw + (size_t)l*Hz*4*Hz, fcb + (size_t)l*4*Hz, nullptr,
            pmlp, M, 4*Hz, Hz, 1|4);
        gemm_tc_kernel<64,64,4><<<dim3(Hz/64, M/64), 256, SM64>>>(
            pmlp, mprojw + (size_t)l*4*Hz*Hz, mprojb + (size_t)l*Hz, ph,
            ph, M, Hz, 4*Hz, 1|2);
    }

    // final groupnorm fused with concat (writes both cat slots directly)
    groupnorm_kernel<true><<<Bz*Gz/2, 256>>>(ph, pcat, lnfw, lnfb);

    const int Mh = Bz * (Sz - 1);  // 1504
    gemm_t_tc_kernel<<<dim3(2*Hz/128, (Mh + 127)/128), 256, SMT>>>(
        pcat, a1w, a1b, pa1, Mh, 2*Hz, 2*Hz, 1|8);
    gemm_t_tc_kernel<<<dim3(CVz/128, (Mh + 127)/128), 256, SMT>>>(
        pa1, a2w, a2b, out, Mh, CVz, 2*Hz, 1|16);
}

// round 17
// speedup vs baseline: 1.0305x; 1.0305x over previous
#include <cuda_runtime.h>
#include <math.h>
#include <stdint.h>

#define Bz  32
#define Sz  48
#define Vz  10000
#define CVz 9600
#define Hz  768
#define NHz 12
#define NLz 12
#define Gz  32
#define HDz 64
#define CPG (Hz/Gz)   // 24

// ------------------------- scratch (no allocation allowed) -------------------------
__device__ float g_h  [Bz*Sz*Hz];
__device__ float g_x  [Bz*Sz*Hz];
__device__ float g_qkv[Bz*Sz*3*Hz];
__device__ float g_a  [Bz*Sz*Hz];
__device__ float g_mlp[Bz*Sz*4*Hz];
__device__ float g_cat[Bz*(Sz-1)*2*Hz];
__device__ float g_a1 [Bz*(Sz-1)*2*Hz];

// ------------------------- helpers -------------------------
__device__ __forceinline__ void mma_tf32(float c[4],
                                         uint32_t a0, uint32_t a1, uint32_t a2, uint32_t a3,
                                         uint32_t b0, uint32_t b1) {
    asm volatile(
        "mma.sync.aligned.m16n8k8.row.col.f32.tf32.tf32.f32 "
        "{%0,%1,%2,%3},{%4,%5,%6,%7},{%8,%9},{%0,%1,%2,%3};"
        : "+f"(c[0]), "+f"(c[1]), "+f"(c[2]), "+f"(c[3])
        : "r"(a0), "r"(a1), "r"(a2), "r"(a3), "r"(b0), "r"(b1));
}

__device__ __forceinline__ void cp_async16(void* smem, const void* gmem, bool pred) {
    uint32_t s = (uint32_t)__cvta_generic_to_shared(smem);
    int src_bytes = pred ? 16 : 0;   // 0 -> zero-fill
    asm volatile("cp.async.cg.shared.global [%0], [%1], 16, %2;\n"
                 :: "r"(s), "l"(gmem), "r"(src_bytes));
}
__device__ __forceinline__ void cp_commit() { asm volatile("cp.async.commit_group;\n"); }
__device__ __forceinline__ void cp_wait2()  { asm volatile("cp.async.wait_group 2;\n"); }

__device__ __forceinline__ float tanh_fast(float x) {
    float y;
    asm("tanh.approx.f32 %0, %1;" : "=f"(y) : "f"(x));
    return y;
}

__device__ __forceinline__ float apply_act(float v, const float* __restrict__ bias,
                                           const float* __restrict__ res,
                                           int gr, int gc, int N, int mode) {
    if (mode & 1)  v += bias[gc];
    if (mode & 2)  v += res[(size_t)gr * N + gc];
    if (mode & 4) {                       // gelu via HW tanh.approx
        float x = v;
        float th = tanh_fast(0.7978845608028654f * (x + 0.044715f * x * x * x));
        v = 0.5f * x * (1.f + th);
    }
    if (mode & 8)  v = fmaxf(v, 0.f);
    if (mode & 16) v = 0.5f + 0.5f * tanh_fast(0.5f * v);  // sigmoid via tanh
    return v;
}

// ------------------- sparse embedding + pos embed (float4 scan + gather) -------------------
__global__ void embed_kernel(const float* __restrict__ visits,
                             const float* __restrict__ vemb,
                             const float* __restrict__ pemb,
                             float* __restrict__ out)
{
    int row = blockIdx.x;            // b*Sz + s
    int s   = row % Sz;
    const float4* vrow4 = (const float4*)(visits + (size_t)row * Vz);
    int t = threadIdx.x;             // 192 threads
    const float4* pemb4 = (const float4*)pemb;
    const float4* vemb4 = (const float4*)vemb;
    float4 acc = pemb4[s * 192 + t];

    __shared__ int   s_idx[768];
    __shared__ float s_val[768];
    __shared__ int   wcnt[6];

    int lane = t & 31, w = t >> 5;   // 6 warps
    const int V4 = Vz / 4;           // 2500

    for (int base = 0; base < V4; base += 192) {
        __syncthreads();
        int v4 = base + t;
        float4 val = (v4 < V4) ? vrow4[v4] : make_float4(0.f, 0.f, 0.f, 0.f);
        int nz = (val.x != 0.f) + (val.y != 0.f) + (val.z != 0.f) + (val.w != 0.f);
        int pre = nz;
#pragma unroll
        for (int o = 1; o < 32; o <<= 1) {
            int up = __shfl_up_sync(0xffffffffu, pre, o);
            if (lane >= o) pre += up;
        }
        int wtot = __shfl_sync(0xffffffffu, pre, 31);
        if (lane == 31) wcnt[w] = wtot;
        __syncthreads();
        int off = pre - nz;
#pragma unroll
        for (int i = 0; i < 6; i++) { if (i < w) off += wcnt[i]; }
        int cnt = 0;
#pragma unroll
        for (int i = 0; i < 6; i++) cnt += wcnt[i];
        if (nz) {
            int p = off;
            int vb = v4 * 4;
            if (val.x != 0.f) { s_idx[p] = vb;     s_val[p] = val.x; p++; }
            if (val.y != 0.f) { s_idx[p] = vb + 1; s_val[p] = val.y; p++; }
            if (val.z != 0.f) { s_idx[p] = vb + 2; s_val[p] = val.z; p++; }
            if (val.w != 0.f) { s_idx[p] = vb + 3; s_val[p] = val.w; p++; }
        }
        __syncthreads();
        for (int j = 0; j < cnt; j++) {
            float4 er = vemb4[(size_t)s_idx[j] * 192 + t];
            float vv = s_val[j];
            acc.x += vv * er.x; acc.y += vv * er.y;
            acc.z += vv * er.z; acc.w += vv * er.w;
        }
    }
    ((float4*)(out + (size_t)row * Hz))[t] = acc;
}

// ---------------- group norm: single pass, register-cached, 4 groups per CTA ----------------
// 512 threads: quarter q = t>>7 handles group 4*blockIdx.x + q with 128 threads.
template<bool CAT>
__global__ void groupnorm_kernel(const float* __restrict__ in, float* __restrict__ out,
                                 const float* __restrict__ w, const float* __restrict__ b)
{
    int t = threadIdx.x;             // 512
    int quart = t >> 7;              // 0..3
    int tl = t & 127;
    int bg = blockIdx.x * 4 + quart;
    int bt = bg / Gz, g = bg % Gz;
    int lane = tl & 31, wid = tl >> 5;   // warp within quarter: 0..3
    const int NELEM = Sz * CPG;      // 1152

    float4 v0, v1, v2;
    int i0 = tl, i1 = tl + 128, i2 = tl + 256;
    {
        int s = i0 / 6, c4 = i0 % 6;
        v0 = *(const float4*)&in[((size_t)bt*Sz + s)*Hz + g*CPG + c4*4];
        s = i1 / 6; c4 = i1 % 6;
        v1 = *(const float4*)&in[((size_t)bt*Sz + s)*Hz + g*CPG + c4*4];
        if (tl < 32) {
            s = i2 / 6; c4 = i2 % 6;
            v2 = *(const float4*)&in[((size_t)bt*Sz + s)*Hz + g*CPG + c4*4];
        }
    }
    float sum = v0.x+v0.y+v0.z+v0.w + v1.x+v1.y+v1.z+v1.w;
    float sq  = v0.x*v0.x+v0.y*v0.y+v0.z*v0.z+v0.w*v0.w
              + v1.x*v1.x+v1.y*v1.y+v1.z*v1.z+v1.w*v1.w;
    if (tl < 32) {
        sum += v2.x+v2.y+v2.z+v2.w;
        sq  += v2.x*v2.x+v2.y*v2.y+v2.z*v2.z+v2.w*v2.w;
    }
#pragma unroll
    for (int o = 16; o > 0; o >>= 1) {
        sum += __shfl_xor_sync(0xffffffffu, sum, o);
        sq  += __shfl_xor_sync(0xffffffffu, sq,  o);
    }
    __shared__ float r1[16], r2[16];
    if (lane == 0) { r1[quart*4 + wid] = sum; r2[quart*4 + wid] = sq; }
    __syncthreads();
    float tot  = r1[quart*4+0] + r1[quart*4+1] + r1[quart*4+2] + r1[quart*4+3];
    float tot2 = r2[quart*4+0] + r2[quart*4+1] + r2[quart*4+2] + r2[quart*4+3];
    float mean = tot / NELEM;
    float var  = tot2 / NELEM - mean*mean;
    float inv  = rsqrtf(var + 1e-5f);

    auto emit = [&](int idx, float4 v) {
        int s = idx / 6, c4 = idx % 6;
        int ch = g*CPG + c4*4;
        float4 o4;
        o4.x = (v.x - mean) * inv * w[ch+0] + b[ch+0];
        o4.y = (v.y - mean) * inv * w[ch+1] + b[ch+1];
        o4.z = (v.z - mean) * inv * w[ch+2] + b[ch+2];
        o4.w = (v.w - mean) * inv * w[ch+3] + b[ch+3];
        if (!CAT) {
            *(float4*)&out[((size_t)bt*Sz + s)*Hz + ch] = o4;
        } else {
            if (s < Sz-1)
                *(float4*)&out[((size_t)(bt*(Sz-1) + s))*2*Hz + ch] = o4;
            if (s > 0)
                *(float4*)&out[((size_t)(bt*(Sz-1) + s - 1))*2*Hz + Hz + ch] = o4;
        }
    };
    emit(i0, v0);
    emit(i1, v1);
    if (tl < 32) emit(i2, v2);
}

// ==================== 4-stage pipelined tf32 GEMM — permuted-k fragments ====================
// Physical k for mma slot (tig, half, step s) = 4*tig + 2*s + half.
#define STG  4

template<int BM, int BN, int MINB>
__global__ __launch_bounds__(256, MINB)
void gemm_tc_kernel(const float* __restrict__ A, const float* __restrict__ W,
                    const float* __restrict__ bias, const float* __restrict__ res,
                    float* __restrict__ C, int M, int N, int K, int mode)
{
    constexpr int WN = BN / 32;
    constexpr int WM = 8 / WN;
    constexpr int MI = BM / (WM * 16);
    constexpr int A_ELE = BM * 16;
    constexpr int B_ELE = 16 * BN;
    extern __shared__ float smem[];
    float* sAb = smem;                 // [STG][BM][16]
    float* sBb = smem + STG * A_ELE;   // [STG][16][BN] (chunk-swizzled)

    int t = threadIdx.x;
    int bm = blockIdx.y * BM;
    int bn = blockIdx.x * BN;
    int lane = t & 31, w = t >> 5;
    int wm = w % WM, wn = w / WM;
    int m_base = wm * (BM / WM), n_base = wn * 32;
    int g = lane >> 2, tig = lane & 3;
    const int xorv = 2 * tig;

    float acc[MI][4][4];
#pragma unroll
    for (int i = 0; i < MI; i++)
#pragma unroll
        for (int j = 0; j < 4; j++)
#pragma unroll
            for (int q = 0; q < 4; q++) acc[i][j][q] = 0.f;

    const int KT = K / 16;

    auto load_tile = [&](int st, int kt) {
        int k0 = kt * 16;
        float* sA = sAb + st * A_ELE;
        float* sB = sBb + st * B_ELE;
#pragma unroll
        for (int idx = t; idx < BM * 4; idx += 256) {
            int mr = idx >> 2;
            int c  = idx & 3;
            cp_async16(sA + mr * 16 + c * 4, A + (size_t)(bm + mr) * K + k0 + c * 4, bm + mr < M);
        }
#pragma unroll
        for (int idx = t; idx < BN * 4; idx += 256) {
            int kr = idx / (BN / 4);
            int nc = idx % (BN / 4);
            int nc2 = nc ^ ((2 * (kr >> 2)) & 7);
            cp_async16(sB + kr * BN + nc2 * 4, W + (size_t)(k0 + kr) * N + bn + nc * 4, true);
        }
    };

#pragma unroll
    for (int s = 0; s < 3; s++) { load_tile(s, s); cp_commit(); }

    for (int kt = 0; kt < KT; kt++) {
        cp_wait2();
        __syncthreads();
        if (kt + 3 < KT) load_tile((kt + 3) & 3, kt + 3);
        cp_commit();

        const float* sA = sAb + (kt & 3) * A_ELE;
        const float* sB = sBb + (kt & 3) * B_ELE;

        float4 fa[MI][2];
#pragma unroll
        for (int mi = 0; mi < MI; mi++) {
            int m0 = m_base + mi * 16;
            fa[mi][0] = *(const float4*)(sA + (m0 + g    ) * 16 + 4 * tig);
            fa[mi][1] = *(const float4*)(sA + (m0 + g + 8) * 16 + 4 * tig);
        }
#pragma unroll
        for (int s = 0; s < 2; s++) {
            int kb = 4 * tig + 2 * s;
            uint32_t bf[4][2];
#pragma unroll
            for (int ni = 0; ni < 4; ni++) {
                int chunk = ((n_base + ni * 8) >> 2) + (g >> 2);
                int col = ((chunk ^ xorv) << 2) + (g & 3);
                bf[ni][0] = __float_as_uint(sB[kb * BN + col]);
                bf[ni][1] = __float_as_uint(sB[(kb + 1) * BN + col]);
            }
#pragma unroll
            for (int mi = 0; mi < MI; mi++) {
                uint32_t a0 = __float_as_uint(s ? fa[mi][0].z : fa[mi][0].x);
                uint32_t a1 = __float_as_uint(s ? fa[mi][1].z : fa[mi][1].x);
                uint32_t a2 = __float_as_uint(s ? fa[mi][0].w : fa[mi][0].y);
                uint32_t a3 = __float_as_uint(s ? fa[mi][1].w : fa[mi][1].y);
#pragma unroll
                for (int ni = 0; ni < 4; ni++)
                    mma_tf32(acc[mi][ni], a0, a1, a2, a3, bf[ni][0], bf[ni][1]);
            }
        }
    }

    // epilogue
#pragma unroll
    for (int mi = 0; mi < MI; mi++) {
        int gr0 = bm + m_base + mi * 16 + g;
        int gr1 = gr0 + 8;
#pragma unroll
        for (int ni = 0; ni < 4; ni++) {
            int gc = bn + n_base + ni * 8 + 2 * tig;
            if (gr0 < M) {
                float v0 = apply_act(acc[mi][ni][0], bias, res, gr0, gc,     N, mode);
                float v1 = apply_act(acc[mi][ni][1], bias, res, gr0, gc + 1, N, mode);
                *(float2*)(C + (size_t)gr0 * N + gc) = make_float2(v0, v1);
            }
            if (gr1 < M) {
                float v2 = apply_act(acc[mi][ni][2], bias, res, gr1, gc,     N, mode);
                float v3 = apply_act(acc[mi][ni][3], bias, res, gr1, gc + 1, N, mode);
                *(float2*)(C + (size_t)gr1 * N + gc) = make_float2(v2, v3);
            }
        }
    }
}

// ======== masked-transposed GEMM (head): C = act(A[M,K] @ (tril(W[N,K]))^T + bias) ========
__global__ __launch_bounds__(256, 2)
void gemm_t_tc_kernel(const float* __restrict__ A, const float* __restrict__ Wr,
                      const float* __restrict__ bias,
                      float* __restrict__ C, int M, int N, int K, int mode)
{
    constexpr int BM = 128, MI = 4;
    constexpr int A_ELE = 128 * 16;
    extern __shared__ float smem[];
    float* sAb  = smem;
    float* sBTb = smem + STG * A_ELE;   // [STG][128][16] ([n][k])

    int t = threadIdx.x;
    int bm = blockIdx.y * BM;
    int bn = blockIdx.x * 128;
    int lane = t & 31, w = t >> 5;
    int wm = w & 1, wn = w >> 1;
    int m_base = wm * 64, n_base = wn * 32;
    int g = lane >> 2, tig = lane & 3;
    const bool need_mask = (bn < K);

    float acc[MI][4][4];
#pragma unroll
    for (int i = 0; i < MI; i++)
#pragma unroll
        for (int j = 0; j < 4; j++)
#pragma unroll
            for (int q = 0; q < 4; q++) acc[i][j][q] = 0.f;

    int KT = K / 16;
    if (need_mask) {
        int need = (bn + 127) / 16 + 1;
        KT = KT < need ? KT : need;
    }

    auto load_tile = [&](int st, int kt) {
        int k0 = kt * 16;
        float* sA  = sAb  + st * A_ELE;
        float* sBT = sBTb + st * A_ELE;
#pragma unroll
        for (int it = 0; it < 2; it++) {
            int idx = it * 256 + t;
            int mr = idx >> 2;
            int c  = idx & 3;
            cp_async16(sA + mr * 16 + c * 4, A + (size_t)(bm + mr) * K + k0 + c * 4, bm + mr < M);
        }
#pragma unroll
        for (int it = 0; it < 2; it++) {
            int idx = it * 256 + t;
            int n  = idx >> 2;
            int c  = idx & 3;
            cp_async16(sBT + n * 16 + c * 4, Wr + (size_t)(bn + n) * K + k0 + c * 4, true);
        }
    };

#pragma unroll
    for (int s = 0; s < 3; s++) { load_tile(s, s); cp_commit(); }

    for (int kt = 0; kt < KT; kt++) {
        cp_wait2();
        __syncthreads();
        if (kt + 3 < KT) load_tile((kt + 3) & 3, kt + 3);
        cp_commit();

        int k0 = kt * 16;
        const float* sA  = sAb  + (kt & 3) * A_ELE;
        const float* sBT = sBTb + (kt & 3) * A_ELE;

        float4 fa[MI][2];
#pragma unroll
        for (int mi = 0; mi < MI; mi++) {
            int m0 = m_base + mi * 16;
            fa[mi][0] = *(const float4*)(sA + (m0 + g    ) * 16 + 4 * tig);
            fa[mi][1] = *(const float4*)(sA + (m0 + g + 8) * 16 + 4 * tig);
        }
        float4 fb[4];
        int kb = k0 + 4 * tig;
#pragma unroll
        for (int ni = 0; ni < 4; ni++) {
            int nl = n_base + ni * 8 + g;
            fb[ni] = *(const float4*)(sBT + nl * 16 + 4 * tig);
            if (need_mask) {
                int gn = bn + nl;
                if (kb     > gn) fb[ni].x = 0.f;
                if (kb + 1 > gn) fb[ni].y = 0.f;
                if (kb + 2 > gn) fb[ni].z = 0.f;
                if (kb + 3 > gn) fb[ni].w = 0.f;
            }
        }
#pragma unroll
        for (int s = 0; s < 2; s++) {
#pragma unroll
            for (int mi = 0; mi < MI; mi++) {
                uint32_t a0 = __float_as_uint(s ? fa[mi][0].z : fa[mi][0].x);
                uint32_t a1 = __float_as_uint(s ? fa[mi][1].z : fa[mi][1].x);
                uint32_t a2 = __float_as_uint(s ? fa[mi][0].w : fa[mi][0].y);
                uint32_t a3 = __float_as_uint(s ? fa[mi][1].w : fa[mi][1].y);
#pragma unroll
                for (int ni = 0; ni < 4; ni++) {
                    uint32_t b0 = __float_as_uint(s ? fb[ni].z : fb[ni].x);
                    uint32_t b1 = __float_as_uint(s ? fb[ni].w : fb[ni].y);
                    mma_tf32(acc[mi][ni], a0, a1, a2, a3, b0, b1);
                }
            }
        }
    }

#pragma unroll
    for (int mi = 0; mi < MI; mi++) {
        int gr0 = bm + m_base + mi * 16 + g;
        int gr1 = gr0 + 8;
#pragma unroll
        for (int ni = 0; ni < 4; ni++) {
            int gc = bn + n_base + ni * 8 + 2 * tig;
            if (gr0 < M) {
                float v0 = apply_act(acc[mi][ni][0], bias, nullptr, gr0, gc,     N, mode);
                float v1 = apply_act(acc[mi][ni][1], bias, nullptr, gr0, gc + 1, N, mode);
                *(float2*)(C + (size_t)gr0 * N + gc) = make_float2(v0, v1);
            }
            if (gr1 < M) {
                float v2 = apply_act(acc[mi][ni][2], bias, nullptr, gr1, gc,     N, mode);
                float v3 = apply_act(acc[mi][ni][3], bias, nullptr, gr1, gc + 1, N, mode);
                *(float2*)(C + (size_t)gr1 * N + gc) = make_float2(v2, v3);
            }
        }
    }
}

// ------------- attention: 6 rows/warp, causal-trimmed QK + PV, warp-local softmax -------------
__global__ void attn_kernel(const float* __restrict__ qkv, float* __restrict__ out)
{
    int bh = blockIdx.x;
    int b = bh / NHz, hd = bh % NHz;
    __shared__ float sq[Sz][68], sk[Sz][68], sv[Sz][68];
    __shared__ float sp[Sz][49];
    int t = threadIdx.x;   // 256
    int lane = t & 31, wid = t >> 5;

    const float* base = qkv + (size_t)b * Sz * (3*Hz) + hd * HDz;
    for (int idx = t; idx < Sz * 16; idx += 256) {
        int s = idx >> 4, d4 = idx & 15;
        const float4* src = (const float4*)(base + (size_t)s * (3*Hz));
        *(float4*)&sq[s][d4*4] = src[d4];
        *(float4*)&sk[s][d4*4] = src[d4 + Hz/4];
        *(float4*)&sv[s][d4*4] = src[d4 + 2*Hz/4];
    }
    __syncthreads();

    const int i0 = wid * 6;
    const int imax = i0 + 5;
    const int j1 = lane, j2 = lane + 32;
    const bool has2 = (j2 <= imax);

    float a0[6] = {0,0,0,0,0,0}, a1r[6] = {0,0,0,0,0,0};
    if (has2) {
#pragma unroll
        for (int d4 = 0; d4 < 16; d4++) {
            float4 k1 = *(const float4*)&sk[j1][d4*4];
            float4 k2 = *(const float4*)&sk[j2][d4*4];
#pragma unroll
            for (int r = 0; r < 6; r++) {
                float4 q = *(const float4*)&sq[i0 + r][d4*4];
                a0[r] += q.x*k1.x + q.y*k1.y + q.z*k1.z + q.w*k1.w;
                a1r[r] += q.x*k2.x + q.y*k2.y + q.z*k2.z + q.w*k2.w;
            }
        }
    } else {
#pragma unroll
        for (int d4 = 0; d4 < 16; d4++) {
            float4 k1 = *(const float4*)&sk[j1][d4*4];
#pragma unroll
            for (int r = 0; r < 6; r++) {
                float4 q = *(const float4*)&sq[i0 + r][d4*4];
                a0[r] += q.x*k1.x + q.y*k1.y + q.z*k1.z + q.w*k1.w;
            }
        }
    }

#pragma unroll
    for (int r = 0; r < 6; r++) {
        int i = i0 + r;
        float s0 = (j1 <= i) ? a0[r] * 0.125f : -1e30f;
        float s1 = (has2 && j2 <= i) ? a1r[r] * 0.125f : -1e30f;
        float mx = fmaxf(s0, s1);
#pragma unroll
        for (int o = 16; o > 0; o >>= 1) mx = fmaxf(mx, __shfl_xor_sync(0xffffffffu, mx, o));
        float e0 = (j1 <= i) ? __expf(s0 - mx) : 0.f;
        float e1 = (has2 && j2 <= i) ? __expf(s1 - mx) : 0.f;
        float sum = e0 + e1;
#pragma unroll
        for (int o = 16; o > 0; o >>= 1) sum += __shfl_xor_sync(0xffffffffu, sum, o);
        float inv = 1.f / sum;
        sp[i][j1] = e0 * inv;
        if (has2) sp[i][j2] = e1 * inv;
    }
    __syncwarp();

    float o0[6] = {0,0,0,0,0,0}, o1[6] = {0,0,0,0,0,0};
    const int jmax = imax + 1;
#pragma unroll 6
    for (int j = 0; j < jmax; j++) {
        float v0 = sv[j][lane];
        float v1 = sv[j][lane + 32];
#pragma unroll
        for (int r = 0; r < 6; r++) {
            float p = sp[i0 + r][j];
            o0[r] += p * v0;
            o1[r] += p * v1;
        }
    }
    float* ob = out + (size_t)b * Sz * Hz + hd * HDz;
#pragma unroll
    for (int r = 0; r < 6; r++) {
        ob[(size_t)(i0 + r) * Hz + lane]      = o0[r];
        ob[(size_t)(i0 + r) * Hz + lane + 32] = o1[r];
    }
}

// ------------------------- launch -------------------------
extern "C" void kernel_launch(void* const* d_in, const int* in_sizes, int n_in,
                              void* d_out, int out_size)
{
    const float* visits = (const float*)d_in[0];
    const float* vemb   = (const float*)d_in[1];
    const float* pemb   = (const float*)d_in[2];
    const float* ln1w   = (const float*)d_in[3];
    const float* ln1b   = (const float*)d_in[4];
    const float* attnw  = (const float*)d_in[5];
    const float* attnb  = (const float*)d_in[6];
    const float* projw  = (const float*)d_in[7];
    const float* projb  = (const float*)d_in[8];
    const float* ln2w   = (const float*)d_in[9];
    const float* ln2b   = (const float*)d_in[10];
    const float* fcw    = (const float*)d_in[11];
    const float* fcb    = (const float*)d_in[12];
    const float* mprojw = (const float*)d_in[13];
    const float* mprojb = (const float*)d_in[14];
    const float* lnfw   = (const float*)d_in[15];
    const float* lnfb   = (const float*)d_in[16];
    const float* a1w    = (const float*)d_in[17];
    const float* a1b    = (const float*)d_in[18];
    const float* a2w    = (const float*)d_in[19];
    const float* a2b    = (const float*)d_in[20];
    float* out = (float*)d_out;

    float *ph, *px, *pqkv, *pa, *pmlp, *pcat, *pa1;
    cudaGetSymbolAddress((void**)&ph,   g_h);
    cudaGetSymbolAddress((void**)&px,   g_x);
    cudaGetSymbolAddress((void**)&pqkv, g_qkv);
    cudaGetSymbolAddress((void**)&pa,   g_a);
    cudaGetSymbolAddress((void**)&pmlp, g_mlp);
    cudaGetSymbolAddress((void**)&pcat, g_cat);
    cudaGetSymbolAddress((void**)&pa1,  g_a1);

    // dynamic smem sizes (4-stage, compact layouts)
    const int SMQ   = STG * ( 96*16 + 16*128) * 4;   // 57344 B (96x128)
    const int SM128 = STG * (128*16 + 16*128) * 4;   // 65536 B
    const int SM64  = STG * ( 64*16 + 16* 64) * 4;   // 32768 B (64x64)
    const int SMT   = STG * (128*16 * 2) * 4;        // 65536 B
    cudaFuncSetAttribute(gemm_tc_kernel<96,128,2>,  cudaFuncAttributeMaxDynamicSharedMemorySize, SMQ);
    cudaFuncSetAttribute(gemm_tc_kernel<128,128,2>, cudaFuncAttributeMaxDynamicSharedMemorySize, SM128);
    cudaFuncSetAttribute(gemm_tc_kernel<64,64,4>,   cudaFuncAttributeMaxDynamicSharedMemorySize, SM64);
    cudaFuncSetAttribute(gemm_t_tc_kernel,          cudaFuncAttributeMaxDynamicSharedMemorySize, SMT);

    const int M = Bz * Sz;   // 1536

    embed_kernel<<<Bz*Sz, 192>>>(visits, vemb, pemb, ph);

    for (int l = 0; l < NLz; l++) {
        groupnorm_kernel<false><<<Bz*Gz/4, 512>>>(ph, px, ln1w + l*Hz, ln1b + l*Hz);
        gemm_tc_kernel<96,128,2><<<dim3(3*Hz/128, M/96), 256, SMQ>>>(
            px, attnw + (size_t)l*Hz*3*Hz, attnb + (size_t)l*3*Hz, nullptr,
            pqkv, M, 3*Hz, Hz, 1);
        attn_kernel<<<Bz*NHz, 256>>>(pqkv, pa);
        gemm_tc_kernel<64,64,4><<<dim3(Hz/64, M/64), 256, SM64>>>(
            pa, projw + (size_t)l*Hz*Hz, projb + (size_t)l*Hz, ph,
            ph, M, Hz, Hz, 1|2);
        groupnorm_kernel<false><<<Bz*Gz/4, 512>>>(ph, px, ln2w + l*Hz, ln2b + l*Hz);
        gemm_tc_kernel<128,128,2><<<dim3(4*Hz/128, M/128), 256, SM128>>>(
            px, fcw + (size_t)l*Hz*4*Hz, fcb + (size_t)l*4*Hz, nullptr,
            pmlp, M, 4*Hz, Hz, 1|4);
        gemm_tc_kernel<64,64,4><<<dim3(Hz/64, M/64), 256, SM64>>>(
            pmlp, mprojw + (size_t)l*4*Hz*Hz, mprojb + (size_t)l*Hz, ph,
            ph, M, Hz, 4*Hz, 1|2);
    }

    // final groupnorm fused with concat (writes both cat slots directly)
    groupnorm_kernel<true><<<Bz*Gz/4, 512>>>(ph, pcat, lnfw, lnfb);

    const int Mh = Bz * (Sz - 1);  // 1504
    gemm_t_tc_kernel<<<dim3(2*Hz/128, (Mh + 127)/128), 256, SMT>>>(
        pcat, a1w, a1b, pa1, Mh, 2*Hz, 2*Hz, 1|8);
    gemm_t_tc_kernel<<<dim3(CVz/128, (Mh + 127)/128), 256, SMT>>>(
        pa1, a2w, a2b, out, Mh, CVz, 2*Hz, 1|16);
}